// round 15
// baseline (speedup 1.0000x reference)
#include <cuda_runtime.h>
#include <math.h>

#define KS        11
#define HALO      5
#define OT        64                 // output tile (square)
#define IN_T      (OT + 2*HALO)      // 74 input tile
#define IMG       512
#define SIN_PITCH (IN_T + 2)         // 76 floats: %4==0 (float4-aligned), not %32 (no bank degeneracy)

__device__ __forceinline__ int reflect_idx(int i) {
    if (i < 0)     return -i;
    if (i >= IMG)  return 2*IMG - 2 - i;
    return i;
}

__global__ __launch_bounds__(256)
void gaussian_blur_kernel(const float* __restrict__ x,
                          const float* __restrict__ sigma,
                          float* __restrict__ out)
{
    __shared__ float s_in[IN_T][SIN_PITCH];   // raw input tile (74 x 74, pitched 76)
    __shared__ float s_h [IN_T][OT];          // horizontally blurred (74 x 64)

    const int tid = threadIdx.y * 32 + threadIdx.x;   // 0..255
    const int tx  = threadIdx.x;                      // 0..31
    const int ty  = threadIdx.y;                      // 0..7

    // ---- 1D normalized Gaussian weights (separable == reference 2D kernel) ----
    float w[KS];
    {
        const float s   = fabsf(sigma[0]) + 1e-6f;
        const float inv = 1.0f / (2.0f * s * s);
        float sum = 0.0f;
        #pragma unroll
        for (int k = 0; k < KS; ++k) {
            const float r = (float)k - (float)HALO;
            w[k] = expf(-r * r * inv);
            sum += w[k];
        }
        const float rs = 1.0f / sum;
        #pragma unroll
        for (int k = 0; k < KS; ++k) w[k] *= rs;
    }

    const long long plane = blockIdx.z;                 // b*C + c, 0..1023
    const float* __restrict__ xp = x   + plane * (long long)(IMG * IMG);
    float*       __restrict__ op = out + plane * (long long)(IMG * IMG);

    const int tile_x = blockIdx.x * OT;
    const int tile_y = blockIdx.y * OT;

    // ---- load 74x74 input tile with reflect padding ----
    #pragma unroll
    for (int r = ty; r < IN_T; r += 8) {
        const int gy = reflect_idx(tile_y + r - HALO);
        const float* __restrict__ row = xp + (long long)gy * IMG;
        #pragma unroll
        for (int c = tx; c < IN_T; c += 32) {
            const int gx = reflect_idx(tile_x + c - HALO);
            s_in[r][c] = row[gx];
        }
    }
    __syncthreads();

    // ---- horizontal pass: 74 rows x 64 cols, 4 outputs/thread from one float4x4 window ----
    // lane16 = tid & 15 -> output cols [4*lane16, 4*lane16+3]; rows strided by 16.
    {
        const int c = (tid & 15) * 4;                 // 0,4,...,60
        #pragma unroll
        for (int r = tid >> 4; r < IN_T; r += 16) {
            float4 a = *(const float4*)&s_in[r][c];
            float4 b = *(const float4*)&s_in[r][c + 4];
            float4 d = *(const float4*)&s_in[r][c + 8];
            float4 e = *(const float4*)&s_in[r][c + 12];
            float f[16] = { a.x, a.y, a.z, a.w,
                            b.x, b.y, b.z, b.w,
                            d.x, d.y, d.z, d.w,
                            e.x, e.y, e.z, e.w };
            float4 o;
            float o0 = 0.f, o1 = 0.f, o2 = 0.f, o3 = 0.f;
            #pragma unroll
            for (int k = 0; k < KS; ++k) {
                o0 = fmaf(w[k], f[k    ], o0);
                o1 = fmaf(w[k], f[k + 1], o1);
                o2 = fmaf(w[k], f[k + 2], o2);
                o3 = fmaf(w[k], f[k + 3], o3);
            }
            o.x = o0; o.y = o1; o.z = o2; o.w = o3;
            *(float4*)&s_h[r][c] = o;
        }
    }
    __syncthreads();

    // ---- vertical pass: 64x64 outputs, 4 row-outputs/thread from one 15-float column window ----
    // col = tid & 63; row group rg = tid >> 6 (0..3), strided by 4 -> rg covers 0..15.
    {
        const int col = tid & 63;
        #pragma unroll
        for (int rg = tid >> 6; rg < 16; rg += 4) {
            const int r0 = rg * 4;
            float f[KS + 3];
            #pragma unroll
            for (int k = 0; k < KS + 3; ++k)
                f[k] = s_h[r0 + k][col];

            float o0 = 0.f, o1 = 0.f, o2 = 0.f, o3 = 0.f;
            #pragma unroll
            for (int k = 0; k < KS; ++k) {
                o0 = fmaf(w[k], f[k    ], o0);
                o1 = fmaf(w[k], f[k + 1], o1);
                o2 = fmaf(w[k], f[k + 2], o2);
                o3 = fmaf(w[k], f[k + 3], o3);
            }
            float* __restrict__ obase = op + (long long)(tile_y + r0) * IMG + tile_x + col;
            obase[0 * IMG] = o0;
            obase[1 * IMG] = o1;
            obase[2 * IMG] = o2;
            obase[3 * IMG] = o3;
        }
    }
}

extern "C" void kernel_launch(void* const* d_in, const int* in_sizes, int n_in,
                              void* d_out, int out_size)
{
    const float* x     = (const float*)d_in[0];   // (16,64,512,512) fp32
    const float* sigma = (const float*)d_in[1];   // (1,) fp32
    float* out = (float*)d_out;

    const int n_planes = in_sizes[0] / (IMG * IMG);   // 16*64 = 1024

    dim3 block(32, 8, 1);
    dim3 grid(IMG / OT, IMG / OT, n_planes);          // 8 x 8 x 1024
    gaussian_blur_kernel<<<grid, block>>>(x, sigma, out);
}

// round 16
// speedup vs baseline: 1.2408x; 1.2408x over previous
#include <cuda_runtime.h>
#include <math.h>

#define KS        11
#define HALO      5
#define OT        64                 // output tile (square)
#define IN_T      (OT + 2*HALO)      // 74 input tile
#define IMG       512
#define SIN_PITCH (IN_T + 2)         // 76 floats: %4==0 (float4-aligned), not %32

__device__ __forceinline__ int reflect_idx(int i) {
    if (i < 0)     return -i;
    if (i >= IMG)  return 2*IMG - 2 - i;
    return i;
}

__global__ __launch_bounds__(256, 8)
void gaussian_blur_kernel(const float* __restrict__ x,
                          const float* __restrict__ sigma,
                          float* __restrict__ out)
{
    // Single tile buffer. Holds raw input (74x74, pitched 76); horizontal pass
    // overwrites cols [0,64) of each row in place (row r's horizontal outputs
    // depend only on row r's inputs).
    __shared__ float s_in[IN_T][SIN_PITCH];

    const int tid = threadIdx.y * 32 + threadIdx.x;   // 0..255
    const int tx  = threadIdx.x;                      // 0..31
    const int ty  = threadIdx.y;                      // 0..7

    // ---- 1D normalized Gaussian weights (separable == reference 2D kernel) ----
    float w[KS];
    {
        const float s   = fabsf(sigma[0]) + 1e-6f;
        const float inv = 1.0f / (2.0f * s * s);
        float sum = 0.0f;
        #pragma unroll
        for (int k = 0; k < KS; ++k) {
            const float r = (float)k - (float)HALO;
            w[k] = expf(-r * r * inv);
            sum += w[k];
        }
        const float rs = 1.0f / sum;
        #pragma unroll
        for (int k = 0; k < KS; ++k) w[k] *= rs;
    }

    const long long plane = blockIdx.z;                 // b*C + c, 0..1023
    const float* __restrict__ xp = x   + plane * (long long)(IMG * IMG);
    float*       __restrict__ op = out + plane * (long long)(IMG * IMG);

    const int tile_x = blockIdx.x * OT;
    const int tile_y = blockIdx.y * OT;

    // ---- load 74x74 input tile with reflect padding ----
    #pragma unroll
    for (int r = ty; r < IN_T; r += 8) {
        const int gy = reflect_idx(tile_y + r - HALO);
        const float* __restrict__ row = xp + (long long)gy * IMG;
        #pragma unroll
        for (int c = tx; c < IN_T; c += 32) {
            const int gx = reflect_idx(tile_x + c - HALO);
            s_in[r][c] = row[gx];
        }
    }
    __syncthreads();

    // ---- horizontal pass, IN PLACE: 74 rows x 64 cols, 4 outputs/thread ----
    // Half-warp (16 lanes) owns a row: lane group covers cols [4L, 4L+3].
    // Output col c (local) = sum_k w[k] * in[local col c+k]  (k=0..10).
    {
        const int c = (tid & 15) * 4;                 // 0,4,...,60
        #pragma unroll
        for (int r = tid >> 4; r < IN_T; r += 16) {
            // read the full 16-float window BEFORE anyone overwrites this row
            const float4 v0 = *(const float4*)&s_in[r][c];
            const float4 v1 = *(const float4*)&s_in[r][c + 4];
            const float4 v2 = *(const float4*)&s_in[r][c + 8];
            const float4 v3 = *(const float4*)&s_in[r][c + 12];

            float o0, o1, o2, o3;
            // v0: i=0..3
            o0 = w[0]*v0.x;
            o0 = fmaf(w[1], v0.y, o0);  o1 = w[0]*v0.y;
            o0 = fmaf(w[2], v0.z, o0);  o1 = fmaf(w[1], v0.z, o1);  o2 = w[0]*v0.z;
            o0 = fmaf(w[3], v0.w, o0);  o1 = fmaf(w[2], v0.w, o1);  o2 = fmaf(w[1], v0.w, o2);  o3 = w[0]*v0.w;
            // v1: i=4..7 (each feeds all 4 outputs)
            o0 = fmaf(w[4], v1.x, o0);  o1 = fmaf(w[3], v1.x, o1);  o2 = fmaf(w[2], v1.x, o2);  o3 = fmaf(w[1], v1.x, o3);
            o0 = fmaf(w[5], v1.y, o0);  o1 = fmaf(w[4], v1.y, o1);  o2 = fmaf(w[3], v1.y, o2);  o3 = fmaf(w[2], v1.y, o3);
            o0 = fmaf(w[6], v1.z, o0);  o1 = fmaf(w[5], v1.z, o1);  o2 = fmaf(w[4], v1.z, o2);  o3 = fmaf(w[3], v1.z, o3);
            o0 = fmaf(w[7], v1.w, o0);  o1 = fmaf(w[6], v1.w, o1);  o2 = fmaf(w[5], v1.w, o2);  o3 = fmaf(w[4], v1.w, o3);
            // v2: i=8..11
            o0 = fmaf(w[8], v2.x, o0);  o1 = fmaf(w[7], v2.x, o1);  o2 = fmaf(w[6], v2.x, o2);  o3 = fmaf(w[5], v2.x, o3);
            o0 = fmaf(w[9], v2.y, o0);  o1 = fmaf(w[8], v2.y, o1);  o2 = fmaf(w[7], v2.y, o2);  o3 = fmaf(w[6], v2.y, o3);
            o0 = fmaf(w[10],v2.z, o0);  o1 = fmaf(w[9], v2.z, o1);  o2 = fmaf(w[8], v2.z, o2);  o3 = fmaf(w[7], v2.z, o3);
                                        o1 = fmaf(w[10],v2.w, o1);  o2 = fmaf(w[9], v2.w, o2);  o3 = fmaf(w[8], v2.w, o3);
            // v3: i=12..13
                                                                    o2 = fmaf(w[10],v3.x, o2);  o3 = fmaf(w[9], v3.x, o3);
                                                                                                o3 = fmaf(w[10],v3.y, o3);

            __syncwarp();                              // all row reads done before in-place write
            float4 o; o.x = o0; o.y = o1; o.z = o2; o.w = o3;
            *(float4*)&s_in[r][c] = o;
        }
    }
    __syncthreads();

    // ---- vertical pass: thread owns 4 consecutive COLS x 1 row per iteration ----
    // acc4 = sum_k w[k] * s_in[r+k][c4..c4+3]; coalesced STG.128.
    {
        const int c4 = (tid & 15) * 4;                // 0,4,...,60
        #pragma unroll
        for (int r = tid >> 4; r < OT; r += 16) {     // 4 iterations
            float4 acc;
            {
                const float4 v = *(const float4*)&s_in[r][c4];
                acc.x = w[0]*v.x; acc.y = w[0]*v.y; acc.z = w[0]*v.z; acc.w = w[0]*v.w;
            }
            #pragma unroll
            for (int k = 1; k < KS; ++k) {
                const float4 v = *(const float4*)&s_in[r + k][c4];
                acc.x = fmaf(w[k], v.x, acc.x);
                acc.y = fmaf(w[k], v.y, acc.y);
                acc.z = fmaf(w[k], v.z, acc.z);
                acc.w = fmaf(w[k], v.w, acc.w);
            }
            *(float4*)(op + (long long)(tile_y + r) * IMG + tile_x + c4) = acc;
        }
    }
}

extern "C" void kernel_launch(void* const* d_in, const int* in_sizes, int n_in,
                              void* d_out, int out_size)
{
    const float* x     = (const float*)d_in[0];   // (16,64,512,512) fp32
    const float* sigma = (const float*)d_in[1];   // (1,) fp32
    float* out = (float*)d_out;

    const int n_planes = in_sizes[0] / (IMG * IMG);   // 16*64 = 1024

    dim3 block(32, 8, 1);
    dim3 grid(IMG / OT, IMG / OT, n_planes);          // 8 x 8 x 1024
    gaussian_blur_kernel<<<grid, block>>>(x, sigma, out);
}